// round 7
// baseline (speedup 1.0000x reference)
#include <cuda_runtime.h>
#include <cuda_fp16.h>
#include <math.h>

#define NN 100000          // nodes
#define NE 3200000         // edges
#define NG 512             // graphs
#define NF 128             // input features
#define BN_EPS 1e-5f

// ---------------- scratch (device globals; no allocations allowed) ----------
__device__ float g_y1[NN * 32];    // x @ W_rel1, padded 30->32 (128B rows)
__device__ float g_agg1[NN * 32];  // init = x @ W_root1 + b1; gather adds edges
__device__ float g_y2[NN * 20];    // h @ W_rel2' (bn1 folded)
__device__ float g_agg2[NN * 20];  // init = h @ W_root2' + b2'; gather adds edges
__device__ int   g_deg[NN];        // in-degree
__device__ int   g_off[NN];        // CSR offsets
__device__ int   g_cur[NN];        // fill cursors
__device__ int   g_csr[NE];        // src ids grouped by dst
__device__ int   g_bsum[128];      // per-block degree sums
__device__ int   g_bpre[128];      // exclusive prefix of block sums

// ---------------- helpers ----------------------------------------------------
__device__ __forceinline__ float2 ffma2(float2 a, float2 b, float2 c) {
    float2 d;
    asm("fma.rn.f32x2 %0, %1, %2, %3;"
        : "=l"(reinterpret_cast<unsigned long long&>(d))
        : "l"(reinterpret_cast<unsigned long long&>(a)),
          "l"(reinterpret_cast<unsigned long long&>(b)),
          "l"(reinterpret_cast<unsigned long long&>(c)));
    return d;
}

// ---------------- CSR construction -------------------------------------------
__global__ void k_zero_deg(int n) {
    int i = blockIdx.x * blockDim.x + threadIdx.x;
    if (i < n) g_deg[i] = 0;
}

__global__ void k_hist(const int* __restrict__ ei, int nE) {
    int e = blockIdx.x * blockDim.x + threadIdx.x;
    if (e >= nE) return;
    atomicAdd(&g_deg[__ldg(&ei[nE + e])], 1);
}

// block-level reduction of g_deg -> g_bsum[block]
__global__ void __launch_bounds__(1024) k_scanA(int n) {
    __shared__ int wsum[32];
    int t = threadIdx.x, lane = t & 31, wid = t >> 5;
    int i = blockIdx.x * 1024 + t;
    int v = (i < n) ? g_deg[i] : 0;
#pragma unroll
    for (int o = 16; o > 0; o >>= 1) v += __shfl_xor_sync(0xffffffffu, v, o);
    if (lane == 0) wsum[wid] = v;
    __syncthreads();
    if (wid == 0) {
        int y = wsum[lane];
#pragma unroll
        for (int o = 16; o > 0; o >>= 1) y += __shfl_xor_sync(0xffffffffu, y, o);
        if (lane == 0) g_bsum[blockIdx.x] = y;
    }
}

// exclusive scan of nb block sums (nb <= 128)
__global__ void __launch_bounds__(128) k_scanB(int nb) {
    __shared__ int sh[128];
    int t = threadIdx.x;
    int v = (t < nb) ? g_bsum[t] : 0;
    sh[t] = v;
    __syncthreads();
    for (int o = 1; o < 128; o <<= 1) {
        int u = (t >= o) ? sh[t - o] : 0;
        __syncthreads();
        sh[t] += u;
        __syncthreads();
    }
    if (t < nb) g_bpre[t] = sh[t] - v;
}

// block-level exclusive scan + global offset -> g_off, g_cur
__global__ void __launch_bounds__(1024) k_scanC(int n) {
    __shared__ int wsum[32];
    int t = threadIdx.x, lane = t & 31, wid = t >> 5;
    int i = blockIdx.x * 1024 + t;
    int v = (i < n) ? g_deg[i] : 0;
    int x = v;
#pragma unroll
    for (int o = 1; o < 32; o <<= 1) {
        int u = __shfl_up_sync(0xffffffffu, x, o);
        if (lane >= o) x += u;
    }
    if (lane == 31) wsum[wid] = x;
    __syncthreads();
    if (wid == 0) {
        int y = wsum[lane];
        int z = y;
#pragma unroll
        for (int o = 1; o < 32; o <<= 1) {
            int u = __shfl_up_sync(0xffffffffu, z, o);
            if (lane >= o) z += u;
        }
        wsum[lane] = z - y;   // exclusive warp offsets
    }
    __syncthreads();
    int excl = g_bpre[blockIdx.x] + wsum[wid] + x - v;
    if (i < n) { g_off[i] = excl; g_cur[i] = excl; }
}

__global__ void k_fill(const int* __restrict__ ei, int nE) {
    int e = blockIdx.x * blockDim.x + threadIdx.x;
    if (e >= nE) return;
    int s = __ldg(&ei[e]);
    int d = __ldg(&ei[nE + e]);
    int pos = atomicAdd(&g_cur[d], 1);
    g_csr[pos] = s;
}

// ---------------- kernel: node transform 1 (128 -> 30 rel + 30 root) --------
__global__ void __launch_bounds__(128) k_node1(
    const float* __restrict__ x,
    const float* __restrict__ Wrel,   // [128,30]
    const float* __restrict__ Wroot,  // [128,30]
    const float* __restrict__ b1,     // [30]
    int n)
{
    __shared__ float Ws[128 * 60];    // row k: [rel 30 | root 30]
    __shared__ float bs[30];
    for (int i = threadIdx.x; i < 128 * 30; i += 128) {
        int k = i / 30, j = i % 30;
        Ws[k * 60 + j]      = Wrel[i];
        Ws[k * 60 + 30 + j] = Wroot[i];
    }
    if (threadIdx.x < 30) bs[threadIdx.x] = b1[threadIdx.x];
    __syncthreads();

    int node = blockIdx.x * 128 + threadIdx.x;
    if (node >= n) return;

    float2 acc[30];
#pragma unroll
    for (int p = 0; p < 30; p++) acc[p] = make_float2(0.f, 0.f);

    const float4* xr = reinterpret_cast<const float4*>(x) + node * 32;
#pragma unroll 4
    for (int k4 = 0; k4 < 32; k4++) {
        float4 xv = __ldg(xr + k4);
#pragma unroll
        for (int q = 0; q < 4; q++) {
            float xs = (q == 0) ? xv.x : (q == 1) ? xv.y : (q == 2) ? xv.z : xv.w;
            float2 xb = make_float2(xs, xs);
            const float4* w4 = reinterpret_cast<const float4*>(&Ws[(k4 * 4 + q) * 60]);
#pragma unroll
            for (int j4 = 0; j4 < 15; j4++) {
                float4 wv = w4[j4];
                acc[j4 * 2]     = ffma2(make_float2(wv.x, wv.y), xb, acc[j4 * 2]);
                acc[j4 * 2 + 1] = ffma2(make_float2(wv.z, wv.w), xb, acc[j4 * 2 + 1]);
            }
        }
    }

    float4* y = reinterpret_cast<float4*>(g_y1 + node * 32);
#pragma unroll
    for (int j4 = 0; j4 < 7; j4++)
        y[j4] = make_float4(acc[j4*2].x, acc[j4*2].y, acc[j4*2+1].x, acc[j4*2+1].y);
    y[7] = make_float4(acc[14].x, acc[14].y, 0.f, 0.f);

    float4* a = reinterpret_cast<float4*>(g_agg1 + node * 32);
#pragma unroll
    for (int j4 = 0; j4 < 7; j4++) {
        float2 p0 = acc[15 + j4*2], p1 = acc[16 + j4*2];
        a[j4] = make_float4(p0.x + bs[j4*4], p0.y + bs[j4*4+1],
                            p1.x + bs[j4*4+2], p1.y + bs[j4*4+3]);
    }
    a[7] = make_float4(acc[29].x + bs[28], acc[29].y + bs[29], 0.f, 0.f);
}

// ---------------- kernel: gather 1 (warp/node, 4 slots x 8 chunks, pipelined)
__global__ void __launch_bounds__(256) k_gather1(int n) {
    int wid = threadIdx.x >> 5, lane = threadIdx.x & 31;
    int node = blockIdx.x * 8 + wid;
    if (node >= n) return;
    int slot = lane >> 3, chunk = lane & 7;
    int start = __ldg(&g_off[node]);
    int deg   = __ldg(&g_deg[node]);
    const float4* Y = reinterpret_cast<const float4*>(g_y1);

    float4 a0 = make_float4(0.f,0.f,0.f,0.f), a1 = make_float4(0.f,0.f,0.f,0.f);
    int i0 = slot, i1 = slot + 4;
    int s0 = (i0 < deg) ? __ldg(&g_csr[start + i0]) : 0;
    int s1 = (i1 < deg) ? __ldg(&g_csr[start + i1]) : 0;
    while (i1 < deg) {
        int n0 = i0 + 8, n1 = i1 + 8;
        int t0 = (n0 < deg) ? __ldg(&g_csr[start + n0]) : 0;
        int t1 = (n1 < deg) ? __ldg(&g_csr[start + n1]) : 0;
        float4 v0 = __ldg(Y + s0 * 8 + chunk);
        float4 v1 = __ldg(Y + s1 * 8 + chunk);
        a0.x += v0.x; a0.y += v0.y; a0.z += v0.z; a0.w += v0.w;
        a1.x += v1.x; a1.y += v1.y; a1.z += v1.z; a1.w += v1.w;
        i0 = n0; i1 = n1; s0 = t0; s1 = t1;
    }
    if (i0 < deg) {
        float4 v0 = __ldg(Y + s0 * 8 + chunk);
        a0.x += v0.x; a0.y += v0.y; a0.z += v0.z; a0.w += v0.w;
    }
    a0.x += a1.x; a0.y += a1.y; a0.z += a1.z; a0.w += a1.w;

    // reduce 4 slots -> slot 0 (lanes 0..7)
    float4 t;
    t.x = __shfl_down_sync(0xffffffffu, a0.x, 16);
    t.y = __shfl_down_sync(0xffffffffu, a0.y, 16);
    t.z = __shfl_down_sync(0xffffffffu, a0.z, 16);
    t.w = __shfl_down_sync(0xffffffffu, a0.w, 16);
    a0.x += t.x; a0.y += t.y; a0.z += t.z; a0.w += t.w;
    t.x = __shfl_down_sync(0xffffffffu, a0.x, 8);
    t.y = __shfl_down_sync(0xffffffffu, a0.y, 8);
    t.z = __shfl_down_sync(0xffffffffu, a0.z, 8);
    t.w = __shfl_down_sync(0xffffffffu, a0.w, 8);
    a0.x += t.x; a0.y += t.y; a0.z += t.z; a0.w += t.w;

    if (lane < 8) {
        float4* p = reinterpret_cast<float4*>(g_agg1) + node * 8 + chunk;
        float4 r = *p;   // init (root + bias) written by node1
        r.x += a0.x; r.y += a0.y; r.z += a0.z; r.w += a0.w;
        *p = r;
    }
}

// ---------------- kernel: node transform 2 (bn1 folded, ffma2) ---------------
__global__ void __launch_bounds__(128) k_node2(
    const float* __restrict__ bn1_g, const float* __restrict__ bn1_b,
    const float* __restrict__ bn1_m, const float* __restrict__ bn1_v,
    const float* __restrict__ Wrel2,   // [30,20]
    const float* __restrict__ Wroot2,  // [30,20]
    const float* __restrict__ b2,      // [20]
    int n)
{
    __shared__ float Ws[30 * 40];
    __shared__ float sc1[30], sh1[30];
    __shared__ float cr[20], cq[20];

    if (threadIdx.x < 30) {
        float sc = bn1_g[threadIdx.x] * rsqrtf(bn1_v[threadIdx.x] + BN_EPS);
        sc1[threadIdx.x] = sc;
        sh1[threadIdx.x] = bn1_b[threadIdx.x] - bn1_m[threadIdx.x] * sc;
    }
    __syncthreads();
    for (int i = threadIdx.x; i < 30 * 20; i += 128) {
        int k = i / 20, j = i % 20;
        Ws[k * 40 + j]      = sc1[k] * Wrel2[i];
        Ws[k * 40 + 20 + j] = sc1[k] * Wroot2[i];
    }
    if (threadIdx.x < 40) {
        int j = threadIdx.x % 20;
        float s = (threadIdx.x < 20) ? 0.f : b2[j];
        if (threadIdx.x < 20) {
            for (int k = 0; k < 30; k++) s += sh1[k] * Wrel2[k * 20 + j];
            cr[j] = s;
        } else {
            for (int k = 0; k < 30; k++) s += sh1[k] * Wroot2[k * 20 + j];
            cq[j] = s;
        }
    }
    __syncthreads();

    int node = blockIdx.x * 128 + threadIdx.x;
    if (node >= n) return;

    float h[30];
    {
        const float4* ar = reinterpret_cast<const float4*>(g_agg1 + node * 32);
#pragma unroll
        for (int k4 = 0; k4 < 8; k4++) {
            float4 v = __ldg(ar + k4);
            if (k4*4+0 < 30) h[k4*4+0] = fmaxf(v.x, 0.f);
            if (k4*4+1 < 30) h[k4*4+1] = fmaxf(v.y, 0.f);
            if (k4*4+2 < 30) h[k4*4+2] = fmaxf(v.z, 0.f);
            if (k4*4+3 < 30) h[k4*4+3] = fmaxf(v.w, 0.f);
        }
    }

    float2 acc[20];
#pragma unroll
    for (int p = 0; p < 10; p++) {
        acc[p]      = make_float2(cr[p*2], cr[p*2+1]);
        acc[10 + p] = make_float2(cq[p*2], cq[p*2+1]);
    }

#pragma unroll
    for (int k = 0; k < 30; k++) {
        float2 xb = make_float2(h[k], h[k]);
        const float4* w4 = reinterpret_cast<const float4*>(&Ws[k * 40]);
#pragma unroll
        for (int j4 = 0; j4 < 10; j4++) {
            float4 wv = w4[j4];
            acc[j4 * 2]     = ffma2(make_float2(wv.x, wv.y), xb, acc[j4 * 2]);
            acc[j4 * 2 + 1] = ffma2(make_float2(wv.z, wv.w), xb, acc[j4 * 2 + 1]);
        }
    }

    float4* y = reinterpret_cast<float4*>(g_y2 + node * 20);
#pragma unroll
    for (int j4 = 0; j4 < 5; j4++)
        y[j4] = make_float4(acc[j4*2].x, acc[j4*2].y, acc[j4*2+1].x, acc[j4*2+1].y);

    float4* a = reinterpret_cast<float4*>(g_agg2 + node * 20);
#pragma unroll
    for (int j4 = 0; j4 < 5; j4++) {
        float2 p0 = acc[10 + j4*2], p1 = acc[11 + j4*2];
        a[j4] = make_float4(p0.x, p0.y, p1.x, p1.y);
    }
}

// ---------------- kernel: gather 2 (warp/node, 6 slots x 5 chunks, pipelined)
__global__ void __launch_bounds__(256) k_gather2(int n) {
    int wid = threadIdx.x >> 5, lane = threadIdx.x & 31;
    int node = blockIdx.x * 8 + wid;
    if (node >= n) return;
    int slot = lane / 5;             // 0..6
    int chunk = lane - slot * 5;     // 0..4
    bool active = lane < 30;
    int start = __ldg(&g_off[node]);
    int deg   = active ? __ldg(&g_deg[node]) : 0;
    const float4* Y = reinterpret_cast<const float4*>(g_y2);

    float4 a0 = make_float4(0.f,0.f,0.f,0.f), a1 = make_float4(0.f,0.f,0.f,0.f);
    int i0 = slot, i1 = slot + 6;
    int s0 = (i0 < deg) ? __ldg(&g_csr[start + i0]) : 0;
    int s1 = (i1 < deg) ? __ldg(&g_csr[start + i1]) : 0;
    while (i1 < deg) {
        int n0 = i0 + 12, n1 = i1 + 12;
        int t0 = (n0 < deg) ? __ldg(&g_csr[start + n0]) : 0;
        int t1 = (n1 < deg) ? __ldg(&g_csr[start + n1]) : 0;
        float4 v0 = __ldg(Y + s0 * 5 + chunk);
        float4 v1 = __ldg(Y + s1 * 5 + chunk);
        a0.x += v0.x; a0.y += v0.y; a0.z += v0.z; a0.w += v0.w;
        a1.x += v1.x; a1.y += v1.y; a1.z += v1.z; a1.w += v1.w;
        i0 = n0; i1 = n1; s0 = t0; s1 = t1;
    }
    if (i0 < deg) {
        float4 v0 = __ldg(Y + s0 * 5 + chunk);
        a0.x += v0.x; a0.y += v0.y; a0.z += v0.z; a0.w += v0.w;
    }
    a0.x += a1.x; a0.y += a1.y; a0.z += a1.z; a0.w += a1.w;

    // reduce 6 slots -> slot 0 (lanes 0..4): +15, then +5 and +10
    float4 t;
    t.x = __shfl_down_sync(0xffffffffu, a0.x, 15);
    t.y = __shfl_down_sync(0xffffffffu, a0.y, 15);
    t.z = __shfl_down_sync(0xffffffffu, a0.z, 15);
    t.w = __shfl_down_sync(0xffffffffu, a0.w, 15);
    a0.x += t.x; a0.y += t.y; a0.z += t.z; a0.w += t.w;
    float4 u5, u10;
    u5.x  = __shfl_down_sync(0xffffffffu, a0.x, 5);
    u5.y  = __shfl_down_sync(0xffffffffu, a0.y, 5);
    u5.z  = __shfl_down_sync(0xffffffffu, a0.z, 5);
    u5.w  = __shfl_down_sync(0xffffffffu, a0.w, 5);
    u10.x = __shfl_down_sync(0xffffffffu, a0.x, 10);
    u10.y = __shfl_down_sync(0xffffffffu, a0.y, 10);
    u10.z = __shfl_down_sync(0xffffffffu, a0.z, 10);
    u10.w = __shfl_down_sync(0xffffffffu, a0.w, 10);
    a0.x += u5.x + u10.x; a0.y += u5.y + u10.y;
    a0.z += u5.z + u10.z; a0.w += u5.w + u10.w;

    if (lane < 5) {
        float4* p = reinterpret_cast<float4*>(g_agg2) + node * 5 + lane;
        float4 r = *p;   // init (root) written by node2
        r.x += a0.x; r.y += a0.y; r.z += a0.z; r.w += a0.w;
        *p = r;
    }
}

// ---------------- kernel: per-graph pooling + MLP head -----------------------
__global__ void __launch_bounds__(32) k_pool_head(
    const int* __restrict__ batch, int n,
    const float* __restrict__ bn2_g, const float* __restrict__ bn2_b,
    const float* __restrict__ bn2_m, const float* __restrict__ bn2_v,
    const float* __restrict__ W1,    // [40,10]
    const float* __restrict__ bl1,   // [10]
    const float* __restrict__ W2,    // [10,1]
    const float* __restrict__ bl2,   // [1]
    float* __restrict__ out)
{
    int g = blockIdx.x;
    int lane = threadIdx.x;

    int lo = 0, hi = n;
    while (lo < hi) { int mid = (lo + hi) >> 1; if (__ldg(&batch[mid]) < g) lo = mid + 1; else hi = mid; }
    int start = lo;
    lo = start; hi = n;
    while (lo < hi) { int mid = (lo + hi) >> 1; if (__ldg(&batch[mid]) < g + 1) lo = mid + 1; else hi = mid; }
    int end = lo;
    int cnt = end - start;

    float sc = 0.f, sh = 0.f;
    if (lane < 20) {
        sc = __ldg(&bn2_g[lane]) * rsqrtf(__ldg(&bn2_v[lane]) + BN_EPS);
        sh = __ldg(&bn2_b[lane]) - __ldg(&bn2_m[lane]) * sc;
    }

    float sum0 = 0.f, sum1 = 0.f, mx0 = -INFINITY, mx1 = -INFINITY;
    if (lane < 20) {
        int nd = start;
        for (; nd + 1 < end; nd += 2) {
            float a0 = __ldg(&g_agg2[nd * 20 + lane]);
            float a1 = __ldg(&g_agg2[(nd + 1) * 20 + lane]);
            float v0 = fmaxf(a0, 0.f) * sc + sh;
            float v1 = fmaxf(a1, 0.f) * sc + sh;
            sum0 += v0; mx0 = fmaxf(mx0, v0);
            sum1 += v1; mx1 = fmaxf(mx1, v1);
        }
        if (nd < end) {
            float a0 = __ldg(&g_agg2[nd * 20 + lane]);
            float v0 = fmaxf(a0, 0.f) * sc + sh;
            sum0 += v0; mx0 = fmaxf(mx0, v0);
        }
    }
    float sum = sum0 + sum1;
    float mx = fmaxf(mx0, mx1);
    float mean = (lane < 20) ? (sum / fmaxf((float)cnt, 1.f)) : 0.f;
    if (cnt == 0 || lane >= 20) mx = 0.f;

    float o = 0.f;
#pragma unroll
    for (int j = 0; j < 10; j++) {
        float p = 0.f;
        if (lane < 20)
            p = mx * __ldg(&W1[lane * 10 + j]) + mean * __ldg(&W1[(lane + 20) * 10 + j]);
#pragma unroll
        for (int off = 16; off > 0; off >>= 1)
            p += __shfl_xor_sync(0xffffffffu, p, off);
        float z = fmaxf(p + __ldg(&bl1[j]), 0.f);
        o += z * __ldg(&W2[j]);
    }
    o += __ldg(&bl2[0]);
    float sig = 1.f / (1.f + expf(-o));
    if (lane == 0) out[g] = sig;
}

// ---------------- launch -----------------------------------------------------
extern "C" void kernel_launch(void* const* d_in, const int* in_sizes, int n_in,
                              void* d_out, int out_size) {
    const float* x      = (const float*)d_in[0];
    const int*   ei     = (const int*)  d_in[1];
    const int*   batch  = (const int*)  d_in[2];
    const float* Wrel1  = (const float*)d_in[3];
    const float* Wroot1 = (const float*)d_in[4];
    const float* b1     = (const float*)d_in[5];
    const float* bn1_g  = (const float*)d_in[6];
    const float* bn1_b  = (const float*)d_in[7];
    const float* bn1_m  = (const float*)d_in[8];
    const float* bn1_v  = (const float*)d_in[9];
    const float* Wrel2  = (const float*)d_in[10];
    const float* Wroot2 = (const float*)d_in[11];
    const float* b2     = (const float*)d_in[12];
    const float* bn2_g  = (const float*)d_in[13];
    const float* bn2_b  = (const float*)d_in[14];
    const float* bn2_m  = (const float*)d_in[15];
    const float* bn2_v  = (const float*)d_in[16];
    const float* W1     = (const float*)d_in[17];
    const float* bl1    = (const float*)d_in[18];
    const float* W2     = (const float*)d_in[19];
    const float* bl2    = (const float*)d_in[20];
    float* out = (float*)d_out;

    int n  = in_sizes[0] / NF;   // nodes
    int nE = in_sizes[1] / 2;    // edges
    int nb = (n + 1023) / 1024;  // scan blocks (<= 128 for n <= NN)

    // ---- CSR build (by destination) ----
    k_zero_deg<<<(n + 255) / 256, 256>>>(n);
    k_hist<<<(nE + 255) / 256, 256>>>(ei, nE);
    k_scanA<<<nb, 1024>>>(n);
    k_scanB<<<1, 128>>>(nb);
    k_scanC<<<nb, 1024>>>(n);
    k_fill<<<(nE + 255) / 256, 256>>>(ei, nE);

    // ---- layer 1 ----
    k_node1<<<(n + 127) / 128, 128>>>(x, Wrel1, Wroot1, b1, n);
    k_gather1<<<(n + 7) / 8, 256>>>(n);

    // ---- layer 2 ----
    k_node2<<<(n + 127) / 128, 128>>>(bn1_g, bn1_b, bn1_m, bn1_v,
                                      Wrel2, Wroot2, b2, n);
    k_gather2<<<(n + 7) / 8, 256>>>(n);

    // ---- pooling + head ----
    k_pool_head<<<NG, 32>>>(batch, n, bn2_g, bn2_b, bn2_m, bn2_v,
                            W1, bl1, W2, bl2, out);
}

// round 10
// speedup vs baseline: 1.7476x; 1.7476x over previous
#include <cuda_runtime.h>
#include <cuda_fp16.h>
#include <math.h>

#define NN 100000          // nodes
#define NE 3200000         // edges
#define NG 512             // graphs
#define NF 128             // input features
#define BN_EPS 1e-5f

// ---------------- scratch (device globals; no allocations allowed) ----------
__device__ __half g_y1h[NN * 32];   // fp16(x @ W_rel1), padded 30->32 (64B rows)
__device__ __half g_agg1h[NN * 32]; // fp16 accumulator: init root+b1; RED adds edges
__device__ float  g_y2[NN * 20];    // h @ W_rel2' (bn1 folded)
__device__ float  g_agg2[NN * 20];  // init = h @ W_root2' + b2'; scatter adds edges

// ---------------- helpers ----------------------------------------------------
__device__ __forceinline__ void red_add_v4_f32(float* p, float4 v) {
    asm volatile("red.global.add.v4.f32 [%0], {%1, %2, %3, %4};"
                 :: "l"(__cvta_generic_to_global(p)),
                    "f"(v.x), "f"(v.y), "f"(v.z), "f"(v.w)
                 : "memory");
}

// 8 fp16 adds in one 16B lane
__device__ __forceinline__ void red_add_v4_f16x2(__half* p, uint4 v) {
    asm volatile("red.global.add.noftz.v4.f16x2 [%0], {%1, %2, %3, %4};"
                 :: "l"(__cvta_generic_to_global(p)),
                    "r"(v.x), "r"(v.y), "r"(v.z), "r"(v.w)
                 : "memory");
}

// packed fp32x2 FMA (sm_100+)
__device__ __forceinline__ float2 ffma2(float2 a, float2 b, float2 c) {
    float2 d;
    asm("fma.rn.f32x2 %0, %1, %2, %3;"
        : "=l"(reinterpret_cast<unsigned long long&>(d))
        : "l"(reinterpret_cast<unsigned long long&>(a)),
          "l"(reinterpret_cast<unsigned long long&>(b)),
          "l"(reinterpret_cast<unsigned long long&>(c)));
    return d;
}

// ---------------- kernel 1: node transform 1 (128 -> 30 rel + 30 root) ------
// g_y1h = fp16(x @ W_rel1) ; g_agg1h = fp16(x @ W_root1 + b1)
__global__ void __launch_bounds__(128) k_node1(
    const float* __restrict__ x,
    const float* __restrict__ Wrel,   // [128,30]
    const float* __restrict__ Wroot,  // [128,30]
    const float* __restrict__ b1,     // [30]
    int n)
{
    __shared__ float Ws[128 * 60];    // row k: [rel 30 | root 30]
    __shared__ float bs[30];
    for (int i = threadIdx.x; i < 128 * 30; i += 128) {
        int k = i / 30, j = i % 30;
        Ws[k * 60 + j]      = Wrel[i];
        Ws[k * 60 + 30 + j] = Wroot[i];
    }
    if (threadIdx.x < 30) bs[threadIdx.x] = b1[threadIdx.x];
    __syncthreads();

    int node = blockIdx.x * 128 + threadIdx.x;
    if (node >= n) return;

    float2 acc[30];                   // pairs (2p,2p+1): 0..14 rel, 15..29 root
#pragma unroll
    for (int p = 0; p < 30; p++) acc[p] = make_float2(0.f, 0.f);

    const float4* xr = reinterpret_cast<const float4*>(x) + node * 32;
#pragma unroll 4
    for (int k4 = 0; k4 < 32; k4++) {
        float4 xv = __ldg(xr + k4);
#pragma unroll
        for (int q = 0; q < 4; q++) {
            float xs = (q == 0) ? xv.x : (q == 1) ? xv.y : (q == 2) ? xv.z : xv.w;
            float2 xb = make_float2(xs, xs);
            const float4* w4 = reinterpret_cast<const float4*>(&Ws[(k4 * 4 + q) * 60]);
#pragma unroll
            for (int j4 = 0; j4 < 15; j4++) {
                float4 wv = w4[j4];
                acc[j4 * 2]     = ffma2(make_float2(wv.x, wv.y), xb, acc[j4 * 2]);
                acc[j4 * 2 + 1] = ffma2(make_float2(wv.z, wv.w), xb, acc[j4 * 2 + 1]);
            }
        }
    }

    // y1h = fp16 rel pairs 0..14 (+1 zero pair) -> 16 half2 = 4 uint4
    {
        __half2 h2[16];
#pragma unroll
        for (int p = 0; p < 15; p++) h2[p] = __float22half2_rn(acc[p]);
        h2[15] = __float2half2_rn(0.f);
        uint4* yo = reinterpret_cast<uint4*>(g_y1h + node * 32);
#pragma unroll
        for (int c = 0; c < 4; c++) yo[c] = reinterpret_cast<uint4*>(h2)[c];
    }
    // agg1h init = fp16(root pairs 15..29 + b1) (+1 zero pair)
    {
        __half2 h2[16];
#pragma unroll
        for (int p = 0; p < 15; p++) {
            float2 t = make_float2(acc[15 + p].x + bs[2 * p],
                                   acc[15 + p].y + bs[2 * p + 1]);
            h2[p] = __float22half2_rn(t);
        }
        h2[15] = __float2half2_rn(0.f);
        uint4* ao = reinterpret_cast<uint4*>(g_agg1h + node * 32);
#pragma unroll
        for (int c = 0; c < 4; c++) ao[c] = reinterpret_cast<uint4*>(h2)[c];
    }
}

// ---------------- kernel 2: edge scatter 1 (4 chunk-lanes/edge, fp16 RED) ----
__global__ void __launch_bounds__(256) k_scatter1(const int* __restrict__ ei, int nE)
{
    long long gtid = (long long)blockIdx.x * blockDim.x + threadIdx.x;
    if (gtid >= (long long)nE * 4) return;
    int e = (int)(gtid >> 2);
    int c = (int)(gtid & 3);
    int s = __ldg(&ei[e]);
    int d = __ldg(&ei[nE + e]);
    uint4 v = __ldg(reinterpret_cast<const uint4*>(g_y1h) + s * 4 + c);
    red_add_v4_f16x2(g_agg1h + d * 32 + c * 8, v);
}

// ---------------- kernel 3: node transform 2 (bn1 folded, ffma2) ------------
__global__ void __launch_bounds__(128) k_node2(
    const float* __restrict__ bn1_g, const float* __restrict__ bn1_b,
    const float* __restrict__ bn1_m, const float* __restrict__ bn1_v,
    const float* __restrict__ Wrel2,   // [30,20]
    const float* __restrict__ Wroot2,  // [30,20]
    const float* __restrict__ b2,      // [20]
    int n)
{
    __shared__ float Ws[30 * 40];
    __shared__ float sc1[30], sh1[30];
    __shared__ float cr[20], cq[20];

    if (threadIdx.x < 30) {
        float sc = bn1_g[threadIdx.x] * rsqrtf(bn1_v[threadIdx.x] + BN_EPS);
        sc1[threadIdx.x] = sc;
        sh1[threadIdx.x] = bn1_b[threadIdx.x] - bn1_m[threadIdx.x] * sc;
    }
    __syncthreads();
    for (int i = threadIdx.x; i < 30 * 20; i += 128) {
        int k = i / 20, j = i % 20;
        Ws[k * 40 + j]      = sc1[k] * Wrel2[i];
        Ws[k * 40 + 20 + j] = sc1[k] * Wroot2[i];
    }
    if (threadIdx.x < 40) {
        int j = threadIdx.x % 20;
        float s = (threadIdx.x < 20) ? 0.f : b2[j];
        if (threadIdx.x < 20) {
            for (int k = 0; k < 30; k++) s += sh1[k] * Wrel2[k * 20 + j];
            cr[j] = s;
        } else {
            for (int k = 0; k < 30; k++) s += sh1[k] * Wroot2[k * 20 + j];
            cq[j] = s;
        }
    }
    __syncthreads();

    int node = blockIdx.x * 128 + threadIdx.x;
    if (node >= n) return;

    float h[30];
    {
        uint4 q[4];
        const uint4* ar = reinterpret_cast<const uint4*>(g_agg1h + node * 32);
#pragma unroll
        for (int c = 0; c < 4; c++) q[c] = __ldg(ar + c);
        const __half2* hp = reinterpret_cast<const __half2*>(q);
#pragma unroll
        for (int p = 0; p < 15; p++) {
            float2 f = __half22float2(hp[p]);
            h[2 * p]     = fmaxf(f.x, 0.f);
            h[2 * p + 1] = fmaxf(f.y, 0.f);
        }
    }

    float2 acc[20];                   // pairs (2p,2p+1): 0..9 rel, 10..19 root
#pragma unroll
    for (int p = 0; p < 10; p++) {
        acc[p]      = make_float2(cr[p*2], cr[p*2+1]);
        acc[10 + p] = make_float2(cq[p*2], cq[p*2+1]);
    }

#pragma unroll
    for (int k = 0; k < 30; k++) {
        float2 xb = make_float2(h[k], h[k]);
        const float4* w4 = reinterpret_cast<const float4*>(&Ws[k * 40]);
#pragma unroll
        for (int j4 = 0; j4 < 10; j4++) {
            float4 wv = w4[j4];
            acc[j4 * 2]     = ffma2(make_float2(wv.x, wv.y), xb, acc[j4 * 2]);
            acc[j4 * 2 + 1] = ffma2(make_float2(wv.z, wv.w), xb, acc[j4 * 2 + 1]);
        }
    }

    float4* y = reinterpret_cast<float4*>(g_y2 + node * 20);
#pragma unroll
    for (int j4 = 0; j4 < 5; j4++)
        y[j4] = make_float4(acc[j4*2].x, acc[j4*2].y, acc[j4*2+1].x, acc[j4*2+1].y);

    float4* a = reinterpret_cast<float4*>(g_agg2 + node * 20);
#pragma unroll
    for (int j4 = 0; j4 < 5; j4++) {
        float2 p0 = acc[10 + j4*2], p1 = acc[11 + j4*2];
        a[j4] = make_float4(p0.x, p0.y, p1.x, p1.y);
    }
}

// ---------------- kernel 4: edge scatter 2 (5 chunk-lanes/edge, fp32 RED) ----
__global__ void __launch_bounds__(256) k_scatter2(const int* __restrict__ ei, int nE)
{
    long long gtid = (long long)blockIdx.x * blockDim.x + threadIdx.x;
    if (gtid >= (long long)nE * 5) return;
    unsigned int u = (unsigned int)gtid;
    unsigned int e = u / 5u;
    unsigned int c = u - e * 5u;
    int s = __ldg(&ei[e]);
    int d = __ldg(&ei[nE + e]);
    float4 v = __ldg(reinterpret_cast<const float4*>(g_y2) + s * 5 + c);
    red_add_v4_f32(g_agg2 + d * 20 + c * 4, v);
}

// ---------------- kernel 5: per-graph pooling + MLP head ---------------------
__global__ void __launch_bounds__(32) k_pool_head(
    const int* __restrict__ batch, int n,
    const float* __restrict__ bn2_g, const float* __restrict__ bn2_b,
    const float* __restrict__ bn2_m, const float* __restrict__ bn2_v,
    const float* __restrict__ W1,    // [40,10]
    const float* __restrict__ bl1,   // [10]
    const float* __restrict__ W2,    // [10,1]
    const float* __restrict__ bl2,   // [1]
    float* __restrict__ out)
{
    int g = blockIdx.x;
    int lane = threadIdx.x;

    int lo = 0, hi = n;
    while (lo < hi) { int mid = (lo + hi) >> 1; if (__ldg(&batch[mid]) < g) lo = mid + 1; else hi = mid; }
    int start = lo;
    lo = start; hi = n;
    while (lo < hi) { int mid = (lo + hi) >> 1; if (__ldg(&batch[mid]) < g + 1) lo = mid + 1; else hi = mid; }
    int end = lo;
    int cnt = end - start;

    float sc = 0.f, sh = 0.f;
    if (lane < 20) {
        sc = __ldg(&bn2_g[lane]) * rsqrtf(__ldg(&bn2_v[lane]) + BN_EPS);
        sh = __ldg(&bn2_b[lane]) - __ldg(&bn2_m[lane]) * sc;
    }

    float sum0 = 0.f, sum1 = 0.f, mx0 = -INFINITY, mx1 = -INFINITY;
    if (lane < 20) {
        int nd = start;
        for (; nd + 1 < end; nd += 2) {
            float a0 = __ldg(&g_agg2[nd * 20 + lane]);
            float a1 = __ldg(&g_agg2[(nd + 1) * 20 + lane]);
            float v0 = fmaxf(a0, 0.f) * sc + sh;
            float v1 = fmaxf(a1, 0.f) * sc + sh;
            sum0 += v0; mx0 = fmaxf(mx0, v0);
            sum1 += v1; mx1 = fmaxf(mx1, v1);
        }
        if (nd < end) {
            float a0 = __ldg(&g_agg2[nd * 20 + lane]);
            float v0 = fmaxf(a0, 0.f) * sc + sh;
            sum0 += v0; mx0 = fmaxf(mx0, v0);
        }
    }
    float sum = sum0 + sum1;
    float mx = fmaxf(mx0, mx1);
    float mean = (lane < 20) ? (sum / fmaxf((float)cnt, 1.f)) : 0.f;
    if (cnt == 0 || lane >= 20) mx = 0.f;

    float o = 0.f;
#pragma unroll
    for (int j = 0; j < 10; j++) {
        float p = 0.f;
        if (lane < 20)
            p = mx * __ldg(&W1[lane * 10 + j]) + mean * __ldg(&W1[(lane + 20) * 10 + j]);
#pragma unroll
        for (int off = 16; off > 0; off >>= 1)
            p += __shfl_xor_sync(0xffffffffu, p, off);
        float z = fmaxf(p + __ldg(&bl1[j]), 0.f);
        o += z * __ldg(&W2[j]);
    }
    o += __ldg(&bl2[0]);
    float sig = 1.f / (1.f + expf(-o));
    if (lane == 0) out[g] = sig;
}

// ---------------- launch -----------------------------------------------------
extern "C" void kernel_launch(void* const* d_in, const int* in_sizes, int n_in,
                              void* d_out, int out_size) {
    const float* x      = (const float*)d_in[0];
    const int*   ei     = (const int*)  d_in[1];
    const int*   batch  = (const int*)  d_in[2];
    const float* Wrel1  = (const float*)d_in[3];
    const float* Wroot1 = (const float*)d_in[4];
    const float* b1     = (const float*)d_in[5];
    const float* bn1_g  = (const float*)d_in[6];
    const float* bn1_b  = (const float*)d_in[7];
    const float* bn1_m  = (const float*)d_in[8];
    const float* bn1_v  = (const float*)d_in[9];
    const float* Wrel2  = (const float*)d_in[10];
    const float* Wroot2 = (const float*)d_in[11];
    const float* b2     = (const float*)d_in[12];
    const float* bn2_g  = (const float*)d_in[13];
    const float* bn2_b  = (const float*)d_in[14];
    const float* bn2_m  = (const float*)d_in[15];
    const float* bn2_v  = (const float*)d_in[16];
    const float* W1     = (const float*)d_in[17];
    const float* bl1    = (const float*)d_in[18];
    const float* W2     = (const float*)d_in[19];
    const float* bl2    = (const float*)d_in[20];
    float* out = (float*)d_out;

    int n  = in_sizes[0] / NF;   // nodes
    int nE = in_sizes[1] / 2;    // edges

    k_node1<<<(n + 127) / 128, 128>>>(x, Wrel1, Wroot1, b1, n);
    {
        long long total = (long long)nE * 4;
        k_scatter1<<<(unsigned)((total + 255) / 256), 256>>>(ei, nE);
    }
    k_node2<<<(n + 127) / 128, 128>>>(bn1_g, bn1_b, bn1_m, bn1_v,
                                      Wrel2, Wroot2, b2, n);
    {
        long long total = (long long)nE * 5;
        k_scatter2<<<(unsigned)((total + 255) / 256), 256>>>(ei, nE);
    }
    k_pool_head<<<NG, 32>>>(batch, n, bn2_g, bn2_b, bn2_m, bn2_v,
                            W1, bl1, W2, bl2, out);
}